// round 7
// baseline (speedup 1.0000x reference)
#include <cuda_runtime.h>
#include <math.h>
#include <stdint.h>

// KoLeoLoss — analytic reduction of the flat-stride-diagonal variant.
//
// Math recap (n=1024, d=256): the reference's flat[::n+1]=inf over the
// flattened (n,n,d) tensor excludes the self-pair ONLY at feature k=0,
// and for k=0 excludes exactly j=i. So m[i,k]=0 exactly for k>=1 and
// m[i,0] = min_{j!=i} |y_j - y_i| with y = L2-normalized column 0.
//
//   loss = -( sum_i log(NN_i + eps) + n*(d-1)*log(eps) ) / n
//
// Regime (R1-R6): tiny workload => idle-DVFS clock; phase A's 65536 LDG.128
// are LSU-ISSUE-bound (~512 LDG x 2-4cyc accept per SM = 3-5us at idle
// clock). Fix: cp.async.bulk (TMA engine) streams each CTA's slice with ONE
// instruction; sumsq computed from smem (LDS floor is far cheaper). PDL
// chains the 3 nodes so launch latency stays hidden.

#define KN   1024
#define KD   256
#define KEPS 1e-8f
#define NBLK 128
#define NTHR 256   // 8 warps

__device__ __align__(16) float g_y[KN];     // normalized column-0 values
__device__ __align__(16) float g_part[NBLK];

__device__ __forceinline__ uint32_t smem_u32(const void* p) {
    return (uint32_t)__cvta_generic_to_shared(p);
}
__device__ __forceinline__ void mbar_init(uint32_t mbar, uint32_t cnt) {
    asm volatile("mbarrier.init.shared.b64 [%0], %1;" :: "r"(mbar), "r"(cnt) : "memory");
}
__device__ __forceinline__ void mbar_expect_tx(uint32_t mbar, uint32_t bytes) {
    asm volatile("mbarrier.arrive.expect_tx.shared.b64 _, [%0], %1;"
                 :: "r"(mbar), "r"(bytes) : "memory");
}
__device__ __forceinline__ void bulk_g2s(uint32_t dst, const void* src,
                                         uint32_t bytes, uint32_t mbar) {
    asm volatile(
        "cp.async.bulk.shared::cluster.global.mbarrier::complete_tx::bytes "
        "[%0], [%1], %2, [%3];"
        :: "r"(dst), "l"(src), "r"(bytes), "r"(mbar) : "memory");
}
__device__ __forceinline__ void mbar_wait0(uint32_t mbar) {
    asm volatile(
        "{\n\t.reg .pred P;\n\t"
        "WL%=:\n\t"
        "mbarrier.try_wait.parity.acquire.cta.shared::cta.b64 P, [%0], 0, 0x989680;\n\t"
        "@P bra WD%=;\n\t"
        "bra WL%=;\n\t"
        "WD%=:\n\t}"
        :: "r"(mbar) : "memory");
}

// ---------------- K1: TMA-staged row norms -> g_y ----------------
__global__ void __launch_bounds__(NTHR, 1)
koleo_rownorm_kernel(const float* __restrict__ X) {
    __shared__ __align__(16) float sx[8 * KD];          // 8 KB slice
    __shared__ __align__(8)  unsigned long long mbar;

    const int t    = threadIdx.x;
    const int w    = t >> 5;
    const int lane = t & 31;
    const int b    = blockIdx.x;
    const uint32_t mb = smem_u32(&mbar);

    if (t == 0) mbar_init(mb, 1);
    __syncthreads();
    if (t == 0) {
        mbar_expect_tx(mb, 8 * KD * 4);
        bulk_g2s(smem_u32(sx), X + b * 8 * KD, 8 * KD * 4, mb);
    }
    mbar_wait0(mb);

    // Warp w handles row b*8+w from smem.
    const float4* R = (const float4*)(sx + w * KD);
    float4 a = R[lane];          // lane 0: a.x == X[row, 0]
    float4 c = R[lane + 32];
    float s0 = a.x*a.x + a.y*a.y + a.z*a.z + a.w*a.w;
    float s1 = c.x*c.x + c.y*c.y + c.z*c.z + c.w*c.w;
    float ss = s0 + s1;
    #pragma unroll
    for (int o = 16; o > 0; o >>= 1)
        ss += __shfl_xor_sync(0xFFFFFFFFu, ss, o);
    if (lane == 0) {
        // y = x0 / max(norm, eps); norm >= eps <=> ss >= eps^2.
        float y = (ss >= 1e-16f) ? a.x * rsqrtf(ss) : a.x * 1e8f;
        g_y[b * 8 + w] = y;
    }
    asm volatile("griddepcontrol.launch_dependents;");
}

// ---------------- K2: 1-D NN + per-block partial (warp-per-i) ----------------
__global__ void __launch_bounds__(NTHR, 1)
koleo_nn_kernel() {
    __shared__ __align__(16) float sy[KN];              // 4 KB
    __shared__ float swsum[8];
    __shared__ __align__(8) unsigned long long mbar;

    const int t    = threadIdx.x;
    const int w    = t >> 5;
    const int lane = t & 31;
    const int b    = blockIdx.x;
    const int i    = b * 8 + w;
    const uint32_t mb = smem_u32(&mbar);

    if (t == 0) mbar_init(mb, 1);
    asm volatile("griddepcontrol.wait;" ::: "memory");  // g_y visible
    __syncthreads();
    if (t == 0) {
        mbar_expect_tx(mb, KN * 4);
        bulk_g2s(smem_u32(sy), g_y, KN * 4, mb);
    }
    mbar_wait0(mb);

    const float xi = sy[i];
    float m0 = INFINITY, m1 = INFINITY, m2 = INFINITY, m3 = INFINITY;
    #pragma unroll
    for (int r = 0; r < 32; r += 4) {
        const int j0 = (r + 0) * 32 + lane;
        const int j1 = (r + 1) * 32 + lane;
        const int j2 = (r + 2) * 32 + lane;
        const int j3 = (r + 3) * 32 + lane;
        const float d0 = fabsf(sy[j0] - xi);
        const float d1 = fabsf(sy[j1] - xi);
        const float d2 = fabsf(sy[j2] - xi);
        const float d3 = fabsf(sy[j3] - xi);
        if (j0 != i) m0 = fminf(m0, d0);
        if (j1 != i) m1 = fminf(m1, d1);
        if (j2 != i) m2 = fminf(m2, d2);
        if (j3 != i) m3 = fminf(m3, d3);
    }
    float m = fminf(fminf(m0, m1), fminf(m2, m3));
    // Warp min in one REDUX: float bits are order-preserving for x >= 0.
    unsigned mbits = __reduce_min_sync(0xFFFFFFFFu, __float_as_uint(m));
    if (lane == 0)
        swsum[w] = logf(__uint_as_float(mbits) + KEPS);
    __syncthreads();

    if (t == 0) {
        float blk = 0.0f;                    // fixed-order: deterministic
        #pragma unroll
        for (int k = 0; k < 8; k++) blk += swsum[k];
        g_part[b] = blk;
    }
    __syncthreads();                         // order the store before signal
    asm volatile("griddepcontrol.launch_dependents;");
}

// ---------------- K3: final 128-value sum (1 warp) ----------------
__global__ void __launch_bounds__(32, 1)
koleo_final_kernel(float* __restrict__ out) {
    const int lane = threadIdx.x;
    asm volatile("griddepcontrol.wait;" ::: "memory");

    float4 p = ((const float4*)g_part)[lane];   // 32 lanes x 4 = 128
    float s = (p.x + p.y) + (p.z + p.w);
    #pragma unroll
    for (int o = 16; o > 0; o >>= 1)
        s += __shfl_xor_sync(0xFFFFFFFFu, s, o);
    if (lane == 0) {
        const float cterm = (float)(KN * (KD - 1)) * logf(KEPS);
        out[0] = -(s + cterm) / (float)KN;
    }
}

extern "C" void kernel_launch(void* const* d_in, const int* in_sizes, int n_in,
                              void* d_out, int out_size) {
    (void)in_sizes; (void)n_in; (void)out_size;
    const float* X = (const float*)d_in[0];
    float* out = (float*)d_out;

    cudaLaunchAttribute attr[1];
    attr[0].id = cudaLaunchAttributeProgrammaticStreamSerialization;
    attr[0].val.programmaticStreamSerializationAllowed = 1;

    koleo_rownorm_kernel<<<NBLK, NTHR>>>(X);

    cudaLaunchConfig_t cfg2 = {};
    cfg2.gridDim = dim3(NBLK, 1, 1);
    cfg2.blockDim = dim3(NTHR, 1, 1);
    cfg2.stream = 0;
    cfg2.attrs = attr;
    cfg2.numAttrs = 1;
    cudaLaunchKernelEx(&cfg2, koleo_nn_kernel);

    cudaLaunchConfig_t cfg3 = {};
    cfg3.gridDim = dim3(1, 1, 1);
    cfg3.blockDim = dim3(32, 1, 1);
    cfg3.stream = 0;
    cfg3.attrs = attr;
    cfg3.numAttrs = 1;
    cudaLaunchKernelEx(&cfg3, koleo_final_kernel, out);
}

// round 8
// speedup vs baseline: 1.0286x; 1.0286x over previous
#include <cuda_runtime.h>
#include <math.h>

// KoLeoLoss — analytic reduction of the flat-stride-diagonal variant.
//
// Math recap (n=1024, d=256): the reference's flat[::n+1]=inf over the
// flattened (n,n,d) tensor excludes the self-pair ONLY at feature k=0
// (f = i*d*(n+1)+k ≡ k mod 1025), and for k=0 excludes exactly j=i
// (gcd(d,n+1)=1, n ≡ -1). So m[i,k]=0 exactly for k>=1 and
// m[i,0] = min_{j!=i} |y_j - y_i| with y = L2-normalized column 0.
//
//   loss = -( sum_i log(NN_i + eps) + n*(d-1)*log(eps) ) / n
//
// R1-R7 established: wall time is pinned at ~8.6-9.2us for every structure
// (1/2/3 nodes, spin, cluster, PDL, TMA) => we are at a floor of graph-replay
// overhead + idle-DVFS ramp + one 1MB traversal. This round: the empirically
// best structure (2 plain nodes, R3 = 8.64us) + the micro-optimizations that
// were only ever measured inside slower variants (REDUX warp-min, split
// min-chains, rsqrtf), + PDL on node 2 (neutral-or-better, hides rollout).

#define KN   1024
#define KD   256
#define KEPS 1e-8f
#define NBLK 128
#define NTHR 256   // 8 warps

__device__ __align__(16) float  g_y[KN];
__device__ int                  g_done = 0;
__device__ unsigned long long   g_sum  = 0ull;

// ---------------- K1: row norms -> g_y (warp-per-row) ----------------
__global__ void __launch_bounds__(NTHR, 1)
koleo_rownorm_kernel(const float* __restrict__ X) {
    const int t    = threadIdx.x;
    const int w    = t >> 5;
    const int lane = t & 31;
    const int row  = blockIdx.x * 8 + w;

    const float4* Xr = (const float4*)(X + row * KD);
    float4 a = Xr[lane];          // lane 0: a.x == X[row, 0]
    float4 c = Xr[lane + 32];
    float s0 = a.x*a.x + a.y*a.y + a.z*a.z + a.w*a.w;
    float s1 = c.x*c.x + c.y*c.y + c.z*c.z + c.w*c.w;
    float ss = s0 + s1;
    #pragma unroll
    for (int o = 16; o > 0; o >>= 1)
        ss += __shfl_xor_sync(0xFFFFFFFFu, ss, o);
    if (lane == 0) {
        // y = x0 / max(norm, eps); norm >= eps <=> ss >= eps^2.
        float y = (ss >= 1e-16f) ? a.x * rsqrtf(ss) : a.x * 1e8f;
        g_y[row] = y;
    }
    asm volatile("griddepcontrol.launch_dependents;");
}

// ---------------- K2: 1-D NN + deterministic reduce + finalize ----------------
__global__ void __launch_bounds__(NTHR, 1)
koleo_nn_kernel(float* __restrict__ out) {
    const int t    = threadIdx.x;
    const int w    = t >> 5;
    const int lane = t & 31;
    const int i    = blockIdx.x * 8 + w;

    __shared__ __align__(16) float sy[KN];
    __shared__ long long psum[8];

    asm volatile("griddepcontrol.wait;" ::: "memory");   // g_y visible

    // Stage all of g_y (4 KB): 256 threads x 1 float4.
    ((float4*)sy)[t] = ((const float4*)g_y)[t];
    __syncthreads();

    const float xi = sy[i];
    // Four independent min accumulators -> short serial chain.
    float m0 = INFINITY, m1 = INFINITY, m2 = INFINITY, m3 = INFINITY;
    #pragma unroll
    for (int r = 0; r < 32; r += 4) {
        const int j0 = (r + 0) * 32 + lane;
        const int j1 = (r + 1) * 32 + lane;
        const int j2 = (r + 2) * 32 + lane;
        const int j3 = (r + 3) * 32 + lane;
        const float d0 = fabsf(sy[j0] - xi);
        const float d1 = fabsf(sy[j1] - xi);
        const float d2 = fabsf(sy[j2] - xi);
        const float d3 = fabsf(sy[j3] - xi);
        if (j0 != i) m0 = fminf(m0, d0);
        if (j1 != i) m1 = fminf(m1, d1);
        if (j2 != i) m2 = fminf(m2, d2);
        if (j3 != i) m3 = fminf(m3, d3);
    }
    float m = fminf(fminf(m0, m1), fminf(m2, m3));
    // Warp min in one REDUX: float bits are order-preserving for x >= 0.
    unsigned mbits = __reduce_min_sync(0xFFFFFFFFu, __float_as_uint(m));
    if (lane == 0) {
        const float l = logf(__uint_as_float(mbits) + KEPS);
        psum[w] = (long long)((double)l * 4294967296.0);   // Q32.32
    }
    __syncthreads();

    if (t == 0) {
        long long blk = 0;
        #pragma unroll
        for (int k = 0; k < 8; k++) blk += psum[k];
        // Order-independent integer accumulation: deterministic.
        atomicAdd(&g_sum, (unsigned long long)blk);
        __threadfence();
        const int old = atomicAdd(&g_done, 1);
        if (old == NBLK - 1) {
            const unsigned long long s = atomicAdd(&g_sum, 0ull);
            const double sum_logs = (double)(long long)s / 4294967296.0;
            const double cterm = (double)(KN * (KD - 1)) * log((double)KEPS);
            out[0] = (float)(-(sum_logs + cterm) / (double)KN);
            g_sum  = 0ull;        // reset for next graph replay
            g_done = 0;
            __threadfence();
        }
    }
}

extern "C" void kernel_launch(void* const* d_in, const int* in_sizes, int n_in,
                              void* d_out, int out_size) {
    (void)in_sizes; (void)n_in; (void)out_size;
    const float* X = (const float*)d_in[0];
    float* out = (float*)d_out;

    koleo_rownorm_kernel<<<NBLK, NTHR>>>(X);

    cudaLaunchAttribute attr[1];
    attr[0].id = cudaLaunchAttributeProgrammaticStreamSerialization;
    attr[0].val.programmaticStreamSerializationAllowed = 1;

    cudaLaunchConfig_t cfg = {};
    cfg.gridDim  = dim3(NBLK, 1, 1);
    cfg.blockDim = dim3(NTHR, 1, 1);
    cfg.stream   = 0;
    cfg.attrs    = attr;
    cfg.numAttrs = 1;
    cudaLaunchKernelEx(&cfg, koleo_nn_kernel, out);
}

// round 9
// speedup vs baseline: 1.0627x; 1.0332x over previous
#include <cuda_runtime.h>
#include <math.h>

// KoLeoLoss — analytic reduction of the flat-stride-diagonal variant.
//
// Math recap (n=1024, d=256): the reference's flat[::n+1]=inf over the
// flattened (n,n,d) tensor excludes the self-pair ONLY at feature k=0
// (f = i*d*(n+1)+k ≡ k mod 1025), and for k=0 excludes exactly j=i
// (gcd(d,n+1)=1, n ≡ -1 mod n+1). So m[i,k]=0 exactly for k>=1 and
// m[i,0] = min_{j!=i} |y_j - y_i| with y = L2-normalized column 0.
//
//   loss = -( sum_i log(NN_i + eps) + n*(d-1)*log(eps) ) / n
//
// R1-R8 conclusion: wall time is pinned at ~8.6-9.2us for EVERY structure
// tried (1/2/3 nodes, L2 spin, 8-CTA cluster, PDL, TMA bulk) — this is the
// harness graph-replay + idle-DVFS floor, not kernel work. This final
// version is the best-measured structure (R3: two plain nodes, 8.64us) with
// strictly-instruction-removing trims: REDUX.MIN warp reduction, 4-way
// split min chains, rsqrtf.

#define KN   1024
#define KD   256
#define KEPS 1e-8f
#define NBLK 128
#define NTHR 256   // 8 warps

__device__ __align__(16) float  g_y[KN];
__device__ int                  g_done = 0;
__device__ unsigned long long   g_sum  = 0ull;

// ---------------- K1: row norms -> g_y (warp-per-row) ----------------
__global__ void __launch_bounds__(NTHR, 1)
koleo_rownorm_kernel(const float* __restrict__ X) {
    const int t    = threadIdx.x;
    const int w    = t >> 5;
    const int lane = t & 31;
    const int row  = blockIdx.x * 8 + w;

    const float4* Xr = (const float4*)(X + row * KD);
    float4 a = Xr[lane];          // lane 0: a.x == X[row, 0]
    float4 c = Xr[lane + 32];
    float s0 = a.x*a.x + a.y*a.y + a.z*a.z + a.w*a.w;
    float s1 = c.x*c.x + c.y*c.y + c.z*c.z + c.w*c.w;
    float ss = s0 + s1;
    #pragma unroll
    for (int o = 16; o > 0; o >>= 1)
        ss += __shfl_xor_sync(0xFFFFFFFFu, ss, o);
    if (lane == 0) {
        // y = x0 / max(norm, eps); norm >= eps <=> ss >= eps^2.
        float y = (ss >= 1e-16f) ? a.x * rsqrtf(ss) : a.x * 1e8f;
        g_y[row] = y;
    }
}

// ---------------- K2: 1-D NN + deterministic reduce + finalize ----------------
__global__ void __launch_bounds__(NTHR, 1)
koleo_nn_kernel(float* __restrict__ out) {
    const int t    = threadIdx.x;
    const int w    = t >> 5;
    const int lane = t & 31;
    const int i    = blockIdx.x * 8 + w;

    __shared__ __align__(16) float sy[KN];
    __shared__ long long psum[8];

    // Stage all of g_y (4 KB): 256 threads x 1 float4.
    ((float4*)sy)[t] = ((const float4*)g_y)[t];
    __syncthreads();

    const float xi = sy[i];
    // Four independent min accumulators -> short serial chain.
    float m0 = INFINITY, m1 = INFINITY, m2 = INFINITY, m3 = INFINITY;
    #pragma unroll
    for (int r = 0; r < 32; r += 4) {
        const int j0 = (r + 0) * 32 + lane;
        const int j1 = (r + 1) * 32 + lane;
        const int j2 = (r + 2) * 32 + lane;
        const int j3 = (r + 3) * 32 + lane;
        const float d0 = fabsf(sy[j0] - xi);
        const float d1 = fabsf(sy[j1] - xi);
        const float d2 = fabsf(sy[j2] - xi);
        const float d3 = fabsf(sy[j3] - xi);
        if (j0 != i) m0 = fminf(m0, d0);
        if (j1 != i) m1 = fminf(m1, d1);
        if (j2 != i) m2 = fminf(m2, d2);
        if (j3 != i) m3 = fminf(m3, d3);
    }
    float m = fminf(fminf(m0, m1), fminf(m2, m3));
    // Warp min in one REDUX: float bits are order-preserving for x >= 0.
    unsigned mbits = __reduce_min_sync(0xFFFFFFFFu, __float_as_uint(m));
    if (lane == 0) {
        const float l = logf(__uint_as_float(mbits) + KEPS);
        psum[w] = (long long)((double)l * 4294967296.0);   // Q32.32
    }
    __syncthreads();

    if (t == 0) {
        long long blk = 0;
        #pragma unroll
        for (int k = 0; k < 8; k++) blk += psum[k];
        // Order-independent integer accumulation: deterministic.
        atomicAdd(&g_sum, (unsigned long long)blk);
        __threadfence();
        const int old = atomicAdd(&g_done, 1);
        if (old == NBLK - 1) {
            const unsigned long long s = atomicAdd(&g_sum, 0ull);
            const double sum_logs = (double)(long long)s / 4294967296.0;
            const double cterm = (double)(KN * (KD - 1)) * log((double)KEPS);
            out[0] = (float)(-(sum_logs + cterm) / (double)KN);
            g_sum  = 0ull;        // reset for next graph replay
            g_done = 0;
            __threadfence();
        }
    }
}

extern "C" void kernel_launch(void* const* d_in, const int* in_sizes, int n_in,
                              void* d_out, int out_size) {
    (void)in_sizes; (void)n_in; (void)out_size;
    const float* X = (const float*)d_in[0];
    float* out = (float*)d_out;

    koleo_rownorm_kernel<<<NBLK, NTHR>>>(X);
    koleo_nn_kernel<<<NBLK, NTHR>>>(out);
}